// round 5
// baseline (speedup 1.0000x reference)
#include <cuda_runtime.h>
#include <cuda_bf16.h>
#include <cstdint>

// ---------------- problem constants ----------------
static constexpr int N_SPK = 1024;
static constexpr int N_UTT = 20;
static constexpr int D_EMB = 512;
static constexpr int R_TOT = N_SPK * N_UTT;   // 20480 rows

static constexpr float COS_EPS = 1e-8f;
static constexpr float SIM_EPS = 1e-6f;

// ---------------- GEMM tiling ----------------
static constexpr int BM  = 128;               // rows per CTA
static constexpr int BN  = 128;               // centroid cols per CTA
static constexpr int KC  = 64;                // K chunk (bf16) -> 128B rows in smem
static constexpr int NCH = D_EMB / KC;        // 8 chunks
static constexpr int MTILES = R_TOT / BM;     // 160
static constexpr int NTILES = N_SPK / BN;     // 8
static constexpr int NPART  = NTILES * 2;     // 16 row-sum partials (2 warp_n halves)

// dynamic smem: [A0 16K][B0 16K][A1 16K][B1 16K]
static constexpr int SMEM_DYN = 4 * BM * KC * 2;   // 65536

// ---------------- scratch (device globals; no allocs allowed) ----------------
__device__ __nv_bfloat16 g_E[R_TOT * D_EMB];      // normalized embeddings (bf16)
__device__ __nv_bfloat16 g_C[N_SPK * D_EMB];      // normalized centroids (bf16)
__device__ float         g_diag[R_TOT];           // leave-one-out cosine (fp32)
__device__ float         g_rowsum[NPART][R_TOT];  // partial exp sums

// ---------------- PTX helpers (all plain-sm_103-safe) ----------------
__device__ __forceinline__ uint32_t smem_u32(const void* p) {
    uint32_t a;
    asm("{ .reg .u64 t; cvta.to.shared.u64 t, %1; cvt.u32.u64 %0, t; }"
        : "=r"(a) : "l"(p));
    return a;
}
__device__ __forceinline__ void cp16(uint32_t dst, const void* src) {
    asm volatile("cp.async.cg.shared.global [%0], [%1], 16;"
                 :: "r"(dst), "l"(src));
}
#define CP_COMMIT() asm volatile("cp.async.commit_group;" ::: "memory")
#define CP_WAIT(n)  asm volatile("cp.async.wait_group %0;" :: "n"(n) : "memory")

#define LDSM_X4(r0, r1, r2, r3, addr)                                          \
    asm volatile("ldmatrix.sync.aligned.m8n8.x4.shared.b16 {%0,%1,%2,%3}, [%4];" \
                 : "=r"(r0), "=r"(r1), "=r"(r2), "=r"(r3) : "r"(addr))

__device__ __forceinline__ void mma16816(float* c, const uint32_t* a,
                                         uint32_t b0, uint32_t b1) {
    asm volatile(
        "mma.sync.aligned.m16n8k16.row.col.f32.bf16.bf16.f32 "
        "{%0,%1,%2,%3}, {%4,%5,%6,%7}, {%8,%9}, {%0,%1,%2,%3};"
        : "+f"(c[0]), "+f"(c[1]), "+f"(c[2]), "+f"(c[3])
        : "r"(a[0]), "r"(a[1]), "r"(a[2]), "r"(a[3]), "r"(b0), "r"(b1));
}

// ---------------- block reduce of 3 floats (broadcast) ----------------
__device__ __forceinline__ void block_reduce3(float& a, float& b, float& c,
                                              float* sRed) {
    #pragma unroll
    for (int o = 16; o > 0; o >>= 1) {
        a += __shfl_down_sync(0xFFFFFFFFu, a, o);
        b += __shfl_down_sync(0xFFFFFFFFu, b, o);
        c += __shfl_down_sync(0xFFFFFFFFu, c, o);
    }
    int w = threadIdx.x >> 5, l = threadIdx.x & 31;
    if (l == 0) { sRed[w] = a; sRed[8 + w] = b; sRed[16 + w] = c; }
    __syncthreads();
    if (threadIdx.x == 0) {
        float A = 0.f, B = 0.f, C = 0.f;
        #pragma unroll
        for (int i = 0; i < 8; i++) { A += sRed[i]; B += sRed[8 + i]; C += sRed[16 + i]; }
        sRed[24] = A; sRed[25] = B; sRed[26] = C;
    }
    __syncthreads();
    a = sRed[24]; b = sRed[25]; c = sRed[26];
    __syncthreads();
}

// ============================================================================
// Kernel 1: per-speaker prep — sums, centroid norm, leave-one-out diag,
// normalized embeddings/centroids written to bf16 scratch. grid=N_SPK, 256 thr
// ============================================================================
__global__ void __launch_bounds__(256) prep_kernel(const float* __restrict__ emb) {
    __shared__ float sE[N_UTT * D_EMB];     // 40 KB
    __shared__ float sSum[D_EMB];           // 2 KB
    __shared__ float sRed[32];

    const int n = blockIdx.x;
    const int tid = threadIdx.x;

    const float4* src = reinterpret_cast<const float4*>(emb + (size_t)n * N_UTT * D_EMB);
    float4* dst = reinterpret_cast<float4*>(sE);
    #pragma unroll
    for (int i = tid; i < N_UTT * D_EMB / 4; i += 256) dst[i] = src[i];
    __syncthreads();

    for (int d = tid; d < D_EMB; d += 256) {
        float s = 0.f;
        #pragma unroll
        for (int m = 0; m < N_UTT; m++) s += sE[m * D_EMB + d];
        sSum[d] = s;
    }
    __syncthreads();

    {   // centroid
        float ss = 0.f, d1 = 0.f, d2 = 0.f;
        for (int d = tid; d < D_EMB; d += 256) ss += sSum[d] * sSum[d];
        block_reduce3(ss, d1, d2, sRed);
        float cnorm  = sqrtf(ss) * (1.0f / N_UTT);
        float cscale = 1.0f / (N_UTT * fmaxf(cnorm, COS_EPS));
        for (int d = tid; d < D_EMB; d += 256)
            g_C[(size_t)n * D_EMB + d] = __float2bfloat16(sSum[d] * cscale);
    }

    const float invM1 = 1.0f / (N_UTT - 1);
    for (int m = 0; m < N_UTT; m++) {
        float ee = 0.f, cc = 0.f, ec = 0.f;
        for (int d = tid; d < D_EMB; d += 256) {
            float e  = sE[m * D_EMB + d];
            float ce = (sSum[d] - e) * invM1;
            ee += e * e; cc += ce * ce; ec += e * ce;
        }
        block_reduce3(ee, cc, ec, sRed);
        float inv_e = 1.0f / fmaxf(sqrtf(ee), COS_EPS);
        float inv_c = 1.0f / fmaxf(sqrtf(cc), COS_EPS);
        if (tid == 0) g_diag[n * N_UTT + m] = ec * inv_e * inv_c;
        for (int d = tid; d < D_EMB; d += 256)
            g_E[(size_t)(n * N_UTT + m) * D_EMB + d] =
                __float2bfloat16(sE[m * D_EMB + d] * inv_e);
    }
}

// ---------------- async chunk load into 128B-row XOR-swizzled smem ----------
__device__ __forceinline__ void load_chunk_async(uint32_t As, uint32_t Bs,
                                                 int m_base, int n_base,
                                                 int c, int tid) {
    const int kof = c * KC;
    #pragma unroll
    for (int i = 0; i < 4; i++) {
        int g = tid + i * 256;
        int row = g >> 3, j = g & 7;
        const char* src = reinterpret_cast<const char*>(
            g_E + (size_t)(m_base + row) * D_EMB + kof) + j * 16;
        uint32_t dst = As + row * 128 + ((j * 16) ^ ((row & 7) * 16));
        cp16(dst, src);
    }
    #pragma unroll
    for (int i = 0; i < 4; i++) {
        int g = tid + i * 256;
        int row = g >> 3, j = g & 7;
        const char* src = reinterpret_cast<const char*>(
            g_C + (size_t)(n_base + row) * D_EMB + kof) + j * 16;
        uint32_t dst = Bs + row * 128 + ((j * 16) ^ ((row & 7) * 16));
        cp16(dst, src);
    }
}

// ============================================================================
// Kernel 2: mma.sync bf16 GEMM (128x128, K=512) fused exp-sum epilogue.
// grid = (MTILES, NTILES), block = 256 (8 warps: warp_m = wid&3, warp_n = wid>>2)
// ============================================================================
__global__ void __launch_bounds__(256, 2) gemm_kernel(const float* __restrict__ wp,
                                                      const float* __restrict__ bp) {
    extern __shared__ char dsm[];
    const uint32_t sb = smem_u32(dsm);
    // buf layout: [A0, B0, A1, B1], 16 KB each
    const uint32_t aAddr[2] = { sb,             sb + 32768 };
    const uint32_t bAddr[2] = { sb + 16384,     sb + 49152 };

    const int tid  = threadIdx.x;
    const int wid  = tid >> 5;
    const int lane = tid & 31;
    const int warp_m = wid & 3;         // 0..3 -> 32-row slice
    const int warp_n = wid >> 2;        // 0..1 -> 64-col slice
    const int m_base = blockIdx.x * BM;
    const int n_base = blockIdx.y * BN;

    float acc[2][8][4];
    #pragma unroll
    for (int mi = 0; mi < 2; mi++)
        #pragma unroll
        for (int ni = 0; ni < 8; ni++)
            #pragma unroll
            for (int k = 0; k < 4; k++) acc[mi][ni][k] = 0.f;

    // lane-derived fragment addressing (constant across chunks)
    const int rowA0 = warp_m * 32 + (lane & 15);           // mi adds 16
    const int gA    = lane >> 4;                           // k-half select
    const int rowB0 = warp_n * 64 + (lane & 7) + (((lane >> 4) & 1) << 3); // p adds 16
    const int gBsel = (lane >> 3) & 1;

    load_chunk_async(aAddr[0], bAddr[0], m_base, n_base, 0, tid);
    CP_COMMIT();

    for (int c = 0; c < NCH; c++) {
        const int buf = c & 1;
        if (c + 1 < NCH) {
            load_chunk_async(aAddr[buf ^ 1], bAddr[buf ^ 1], m_base, n_base, c + 1, tid);
            CP_COMMIT();
            CP_WAIT(1);
        } else {
            CP_WAIT(0);
        }
        __syncthreads();

        const uint32_t As = aAddr[buf], Bs = bAddr[buf];
        #pragma unroll
        for (int ks = 0; ks < 4; ks++) {
            uint32_t a[2][4];
            #pragma unroll
            for (int mi = 0; mi < 2; mi++) {
                int rowA = rowA0 + mi * 16;
                uint32_t addr = As + rowA * 128 +
                                (((ks * 2 + gA) * 16) ^ ((rowA & 7) * 16));
                LDSM_X4(a[mi][0], a[mi][1], a[mi][2], a[mi][3], addr);
            }
            #pragma unroll
            for (int p = 0; p < 4; p++) {
                int rowB = rowB0 + p * 16;
                int gB = ks * 2 + gBsel;
                uint32_t addr = Bs + rowB * 128 + ((gB * 16) ^ ((rowB & 7) * 16));
                uint32_t b0, b1, b2, b3;
                LDSM_X4(b0, b1, b2, b3, addr);
                mma16816(acc[0][2 * p],     a[0], b0, b1);
                mma16816(acc[0][2 * p + 1], a[0], b2, b3);
                mma16816(acc[1][2 * p],     a[1], b0, b1);
                mma16816(acc[1][2 * p + 1], a[1], b2, b3);
            }
        }
        __syncthreads();   // protect buf before next-next chunk overwrites it
    }

    // ---- fused epilogue: exp-sum per row with leave-one-out replacement ----
    const float wv  = *wp;
    const float bpr = fmaf(wv, SIM_EPS, *bp);  // w*(cos+eps)+b
    const int l4 = lane >> 2, lm = lane & 3;
    const int colbase = n_base + warp_n * 64 + 2 * lm;
    const int part = blockIdx.y * 2 + warp_n;

    #pragma unroll
    for (int mi = 0; mi < 2; mi++) {
        #pragma unroll
        for (int h = 0; h < 2; h++) {
            const int rg = m_base + warp_m * 32 + mi * 16 + h * 8 + l4;
            const int spk = rg / N_UTT;
            const float dval = g_diag[rg];
            float s = 0.f;
            #pragma unroll
            for (int ni = 0; ni < 8; ni++) {
                #pragma unroll
                for (int cc = 0; cc < 2; cc++) {
                    float cv = acc[mi][ni][2 * h + cc];
                    int col = colbase + ni * 8 + cc;
                    if (col == spk) cv = dval;
                    s += __expf(fmaf(wv, cv, bpr));
                }
            }
            s += __shfl_xor_sync(0xFFFFFFFFu, s, 1);
            s += __shfl_xor_sync(0xFFFFFFFFu, s, 2);
            if (lm == 0) g_rowsum[part][rg] = s;
        }
    }
}

// ============================================================================
// Kernel 3: finalize — loss = sum_r [ log(sum_p rowsum[p][r] + eps) - pos_r ]
// ============================================================================
__global__ void __launch_bounds__(1024) finalize_kernel(const float* __restrict__ wp,
                                                        const float* __restrict__ bp,
                                                        float* __restrict__ out) {
    __shared__ float sRed[32];
    const int tid = threadIdx.x;
    const float wv = *wp, bv = *bp;
    float acc = 0.f;
    for (int r = tid; r < R_TOT; r += 1024) {
        float s = 0.f;
        #pragma unroll
        for (int p = 0; p < NPART; p++) s += g_rowsum[p][r];
        float pos = fmaf(wv, g_diag[r] + SIM_EPS, bv);
        acc += logf(s + SIM_EPS) - pos;
    }
    #pragma unroll
    for (int o = 16; o > 0; o >>= 1) acc += __shfl_down_sync(0xFFFFFFFFu, acc, o);
    if ((tid & 31) == 0) sRed[tid >> 5] = acc;
    __syncthreads();
    if (tid < 32) {
        float v = sRed[tid];
        #pragma unroll
        for (int o = 16; o > 0; o >>= 1) v += __shfl_down_sync(0xFFFFFFFFu, v, o);
        if (tid == 0) out[0] = v;
    }
}

// ============================================================================
extern "C" void kernel_launch(void* const* d_in, const int* in_sizes, int n_in,
                              void* d_out, int out_size) {
    const float* emb = (const float*)d_in[0];
    const float* w   = (const float*)d_in[1];
    const float* b   = (const float*)d_in[2];
    float* out = (float*)d_out;

    cudaFuncSetAttribute(gemm_kernel,
                         cudaFuncAttributeMaxDynamicSharedMemorySize, SMEM_DYN);

    prep_kernel<<<N_SPK, 256>>>(emb);
    gemm_kernel<<<dim3(MTILES, NTILES), 256, SMEM_DYN>>>(w, b);
    finalize_kernel<<<1, 1024>>>(w, b, out);
}

// round 6
// speedup vs baseline: 1.4771x; 1.4771x over previous
#include <cuda_runtime.h>
#include <cuda_bf16.h>
#include <cstdint>

// ---------------- problem constants ----------------
static constexpr int N_SPK = 1024;
static constexpr int N_UTT = 20;
static constexpr int D_EMB = 512;
static constexpr int R_TOT = N_SPK * N_UTT;   // 20480 rows

static constexpr float COS_EPS = 1e-8f;
static constexpr float SIM_EPS = 1e-6f;

// ---------------- GEMM tiling ----------------
static constexpr int BM  = 128;               // rows per CTA
static constexpr int BN  = 128;               // centroid cols per CTA
static constexpr int KC  = 64;                // K chunk (bf16) -> 128B rows in smem
static constexpr int NCH = D_EMB / KC;        // 8 chunks
static constexpr int MTILES = R_TOT / BM;     // 160
static constexpr int NTILES = N_SPK / BN;     // 8
static constexpr int NPART  = NTILES;         // 8 row-sum partial arrays

// 3-stage ring: [A_s 16K | B_s 16K] x 3
static constexpr int STAGE_BYTES = 2 * BM * KC * 2;     // 32768
static constexpr int SMEM_DYN = 3 * STAGE_BYTES;        // 98304

// ---------------- scratch (device globals; no allocs allowed) ----------------
__device__ __nv_bfloat16 g_E[R_TOT * D_EMB];      // normalized embeddings (bf16)
__device__ __nv_bfloat16 g_C[N_SPK * D_EMB];      // normalized centroids (bf16)
__device__ float         g_diag[R_TOT];           // leave-one-out cosine (fp32)
__device__ float         g_rowsum[NPART][R_TOT];  // per n-tile exp sums
__device__ float         g_bsum[40];              // finalize partials

// ---------------- PTX helpers (plain-sm_103-safe) ----------------
__device__ __forceinline__ uint32_t smem_u32(const void* p) {
    uint32_t a;
    asm("{ .reg .u64 t; cvta.to.shared.u64 t, %1; cvt.u32.u64 %0, t; }"
        : "=r"(a) : "l"(p));
    return a;
}
__device__ __forceinline__ void cp16(uint32_t dst, const void* src) {
    asm volatile("cp.async.cg.shared.global [%0], [%1], 16;"
                 :: "r"(dst), "l"(src));
}
#define CP_COMMIT() asm volatile("cp.async.commit_group;" ::: "memory")
#define CP_WAIT(n)  asm volatile("cp.async.wait_group %0;" :: "n"(n) : "memory")

#define LDSM_X4(r0, r1, r2, r3, addr)                                          \
    asm volatile("ldmatrix.sync.aligned.m8n8.x4.shared.b16 {%0,%1,%2,%3}, [%4];" \
                 : "=r"(r0), "=r"(r1), "=r"(r2), "=r"(r3) : "r"(addr))

__device__ __forceinline__ void mma16816(float* c, const uint32_t* a,
                                         uint32_t b0, uint32_t b1) {
    asm volatile(
        "mma.sync.aligned.m16n8k16.row.col.f32.bf16.bf16.f32 "
        "{%0,%1,%2,%3}, {%4,%5,%6,%7}, {%8,%9}, {%0,%1,%2,%3};"
        : "+f"(c[0]), "+f"(c[1]), "+f"(c[2]), "+f"(c[3])
        : "r"(a[0]), "r"(a[1]), "r"(a[2]), "r"(a[3]), "r"(b0), "r"(b1));
}

// ============================================================================
// Kernel 1: per-speaker prep. One block per speaker, 8 warps.
// Work items 0..19 = utterances (warp-local reduce), item 20 = centroid.
// No block barriers inside the item loop.
// ============================================================================
__global__ void __launch_bounds__(256) prep_kernel(const float* __restrict__ emb) {
    __shared__ float sE[N_UTT * D_EMB];     // 40 KB
    __shared__ float sSum[D_EMB];           // 2 KB

    const int n    = blockIdx.x;
    const int tid  = threadIdx.x;
    const int wid  = tid >> 5;
    const int lane = tid & 31;

    // stage speaker block (2560 float4)
    const float4* src = reinterpret_cast<const float4*>(emb + (size_t)n * N_UTT * D_EMB);
    float4* dst = reinterpret_cast<float4*>(sE);
    #pragma unroll
    for (int i = tid; i < N_UTT * D_EMB / 4; i += 256) dst[i] = src[i];
    __syncthreads();

    // per-dim sums (each thread: d = tid, tid+256)
    #pragma unroll
    for (int dd = 0; dd < 2; dd++) {
        int d = tid + dd * 256;
        float s = 0.f;
        #pragma unroll
        for (int m = 0; m < N_UTT; m++) s += sE[m * D_EMB + d];
        sSum[d] = s;
    }
    __syncthreads();

    const float invM1 = 1.0f / (N_UTT - 1);

    for (int item = wid; item <= N_UTT; item += 8) {
        if (item == N_UTT) {
            // centroid: norm of sum, write normalized centroid
            float ss = 0.f;
            #pragma unroll
            for (int i = 0; i < 8; i++) {
                int d = i * 64 + lane * 2;
                float2 v = *reinterpret_cast<const float2*>(&sSum[d]);
                ss += v.x * v.x + v.y * v.y;
            }
            #pragma unroll
            for (int o = 16; o > 0; o >>= 1)
                ss += __shfl_xor_sync(0xFFFFFFFFu, ss, o);
            float cnorm  = sqrtf(ss) * (1.0f / N_UTT);
            float cscale = 1.0f / (N_UTT * fmaxf(cnorm, COS_EPS));
            #pragma unroll
            for (int i = 0; i < 8; i++) {
                int d = i * 64 + lane * 2;
                float2 v = *reinterpret_cast<const float2*>(&sSum[d]);
                __nv_bfloat162 o2;
                o2.x = __float2bfloat16(v.x * cscale);
                o2.y = __float2bfloat16(v.y * cscale);
                *reinterpret_cast<__nv_bfloat162*>(&g_C[(size_t)n * D_EMB + d]) = o2;
            }
        } else {
            const int m = item;
            float ee = 0.f, cc = 0.f, ec = 0.f;
            #pragma unroll
            for (int i = 0; i < 8; i++) {
                int d = i * 64 + lane * 2;
                float2 e  = *reinterpret_cast<const float2*>(&sE[m * D_EMB + d]);
                float2 s2 = *reinterpret_cast<const float2*>(&sSum[d]);
                float cx = (s2.x - e.x) * invM1;
                float cy = (s2.y - e.y) * invM1;
                ee += e.x * e.x + e.y * e.y;
                cc += cx * cx + cy * cy;
                ec += e.x * cx + e.y * cy;
            }
            #pragma unroll
            for (int o = 16; o > 0; o >>= 1) {
                ee += __shfl_xor_sync(0xFFFFFFFFu, ee, o);
                cc += __shfl_xor_sync(0xFFFFFFFFu, cc, o);
                ec += __shfl_xor_sync(0xFFFFFFFFu, ec, o);
            }
            float inv_e = 1.0f / fmaxf(sqrtf(ee), COS_EPS);
            float inv_c = 1.0f / fmaxf(sqrtf(cc), COS_EPS);
            if (lane == 0) g_diag[n * N_UTT + m] = ec * inv_e * inv_c;
            const size_t rowoff = (size_t)(n * N_UTT + m) * D_EMB;
            #pragma unroll
            for (int i = 0; i < 8; i++) {
                int d = i * 64 + lane * 2;
                float2 e = *reinterpret_cast<const float2*>(&sE[m * D_EMB + d]);
                __nv_bfloat162 o2;
                o2.x = __float2bfloat16(e.x * inv_e);
                o2.y = __float2bfloat16(e.y * inv_e);
                *reinterpret_cast<__nv_bfloat162*>(&g_E[rowoff + d]) = o2;
            }
        }
    }
}

// ---------------- async chunk load into 128B-row XOR-swizzled smem ----------
__device__ __forceinline__ void load_chunk_async(uint32_t As, uint32_t Bs,
                                                 int m_base, int n_base,
                                                 int c, int tid) {
    const int kof = c * KC;
    #pragma unroll
    for (int i = 0; i < 4; i++) {
        int g = tid + i * 256;
        int row = g >> 3, j = g & 7;
        const char* src = reinterpret_cast<const char*>(
            g_E + (size_t)(m_base + row) * D_EMB + kof) + j * 16;
        uint32_t dst = As + row * 128 + ((j * 16) ^ ((row & 7) * 16));
        cp16(dst, src);
    }
    #pragma unroll
    for (int i = 0; i < 4; i++) {
        int g = tid + i * 256;
        int row = g >> 3, j = g & 7;
        const char* src = reinterpret_cast<const char*>(
            g_C + (size_t)(n_base + row) * D_EMB + kof) + j * 16;
        uint32_t dst = Bs + row * 128 + ((j * 16) ^ ((row & 7) * 16));
        cp16(dst, src);
    }
}

// ============================================================================
// Kernel 2: mma.sync bf16 GEMM (128x128, K=512), 3-stage cp.async ring,
// one __syncthreads per chunk, fused exp-sum epilogue.
// grid = (MTILES, NTILES), block = 256 (8 warps: warp_m = wid&3, warp_n = wid>>2)
// ============================================================================
__global__ void __launch_bounds__(256, 2) gemm_kernel(const float* __restrict__ wp,
                                                      const float* __restrict__ bp) {
    extern __shared__ char dsm[];
    const uint32_t sb = smem_u32(dsm);
    const uint32_t aAddr[3] = { sb,               sb + STAGE_BYTES,
                                sb + 2 * STAGE_BYTES };
    const uint32_t bAddr[3] = { sb + 16384,       sb + STAGE_BYTES + 16384,
                                sb + 2 * STAGE_BYTES + 16384 };

    const int tid  = threadIdx.x;
    const int wid  = tid >> 5;
    const int lane = tid & 31;
    const int warp_m = wid & 3;
    const int warp_n = wid >> 2;
    const int m_base = blockIdx.x * BM;
    const int n_base = blockIdx.y * BN;

    float acc[2][8][4];
    #pragma unroll
    for (int mi = 0; mi < 2; mi++)
        #pragma unroll
        for (int ni = 0; ni < 8; ni++)
            #pragma unroll
            for (int k = 0; k < 4; k++) acc[mi][ni][k] = 0.f;

    const int rowA0 = warp_m * 32 + (lane & 15);
    const int gA    = lane >> 4;
    const int rowB0 = warp_n * 64 + (lane & 7) + (((lane >> 4) & 1) << 3);
    const int gBsel = (lane >> 3) & 1;

    load_chunk_async(aAddr[0], bAddr[0], m_base, n_base, 0, tid);
    CP_COMMIT();
    load_chunk_async(aAddr[1], bAddr[1], m_base, n_base, 1, tid);
    CP_COMMIT();

    #pragma unroll
    for (int c = 0; c < NCH; c++) {
        if (c + 1 < NCH) { CP_WAIT(1); } else { CP_WAIT(0); }
        __syncthreads();
        if (c + 2 < NCH) {
            const int s = (c + 2) % 3;
            load_chunk_async(aAddr[s], bAddr[s], m_base, n_base, c + 2, tid);
            CP_COMMIT();
        }
        const uint32_t As = aAddr[c % 3], Bs = bAddr[c % 3];
        #pragma unroll
        for (int ks = 0; ks < 4; ks++) {
            uint32_t a[2][4];
            #pragma unroll
            for (int mi = 0; mi < 2; mi++) {
                int rowA = rowA0 + mi * 16;
                uint32_t addr = As + rowA * 128 +
                                (((ks * 2 + gA) * 16) ^ ((rowA & 7) * 16));
                LDSM_X4(a[mi][0], a[mi][1], a[mi][2], a[mi][3], addr);
            }
            #pragma unroll
            for (int p = 0; p < 4; p++) {
                int rowB = rowB0 + p * 16;
                int gB = ks * 2 + gBsel;
                uint32_t addr = Bs + rowB * 128 + ((gB * 16) ^ ((rowB & 7) * 16));
                uint32_t b0, b1, b2, b3;
                LDSM_X4(b0, b1, b2, b3, addr);
                mma16816(acc[0][2 * p],     a[0], b0, b1);
                mma16816(acc[0][2 * p + 1], a[0], b2, b3);
                mma16816(acc[1][2 * p],     a[1], b0, b1);
                mma16816(acc[1][2 * p + 1], a[1], b2, b3);
            }
        }
    }

    // ---- fused epilogue: exp-sum per row, leave-one-out replacement,
    //      combine the two warp_n halves through smem -> one partial per CTA ----
    const float wv  = *wp;
    const float bpr = fmaf(wv, SIM_EPS, *bp);
    const int l4 = lane >> 2, lm = lane & 3;
    const int colbase = n_base + warp_n * 64 + 2 * lm;
    float* sPart = reinterpret_cast<float*>(dsm);   // stage-0 region, safe now

    float rowS[2][2];
    #pragma unroll
    for (int mi = 0; mi < 2; mi++) {
        #pragma unroll
        for (int h = 0; h < 2; h++) {
            const int rg = m_base + warp_m * 32 + mi * 16 + h * 8 + l4;
            const int spk = rg / N_UTT;
            const float dval = g_diag[rg];
            float s = 0.f;
            #pragma unroll
            for (int ni = 0; ni < 8; ni++) {
                #pragma unroll
                for (int cc = 0; cc < 2; cc++) {
                    float cv = acc[mi][ni][2 * h + cc];
                    int col = colbase + ni * 8 + cc;
                    if (col == spk) cv = dval;
                    s += __expf(fmaf(wv, cv, bpr));
                }
            }
            s += __shfl_xor_sync(0xFFFFFFFFu, s, 1);
            s += __shfl_xor_sync(0xFFFFFFFFu, s, 2);
            rowS[mi][h] = s;
        }
    }
    __syncthreads();   // all warps done with smem tiles + ready for sPart
    if (warp_n == 0 && lm == 0) {
        #pragma unroll
        for (int mi = 0; mi < 2; mi++)
            #pragma unroll
            for (int h = 0; h < 2; h++)
                sPart[warp_m * 32 + mi * 16 + h * 8 + l4] = rowS[mi][h];
    }
    __syncthreads();
    if (warp_n == 1 && lm == 0) {
        #pragma unroll
        for (int mi = 0; mi < 2; mi++)
            #pragma unroll
            for (int h = 0; h < 2; h++) {
                const int idx = warp_m * 32 + mi * 16 + h * 8 + l4;
                g_rowsum[blockIdx.y][m_base + idx] = rowS[mi][h] + sPart[idx];
            }
    }
}

// ============================================================================
// Kernel 3a: per-row log-sum-exp minus pos, block-reduced. grid=40 x 512 thr
// ============================================================================
__global__ void __launch_bounds__(512) finalize1_kernel(const float* __restrict__ wp,
                                                        const float* __restrict__ bp) {
    __shared__ float sRed[16];
    const int r = blockIdx.x * 512 + threadIdx.x;
    const float wv = *wp, bv = *bp;
    float s = 0.f;
    #pragma unroll
    for (int p = 0; p < NPART; p++) s += g_rowsum[p][r];
    float acc = logf(s + SIM_EPS) - fmaf(wv, g_diag[r] + SIM_EPS, bv);
    #pragma unroll
    for (int o = 16; o > 0; o >>= 1) acc += __shfl_down_sync(0xFFFFFFFFu, acc, o);
    if ((threadIdx.x & 31) == 0) sRed[threadIdx.x >> 5] = acc;
    __syncthreads();
    if (threadIdx.x < 32) {
        float v = (threadIdx.x < 16) ? sRed[threadIdx.x] : 0.f;
        #pragma unroll
        for (int o = 8; o > 0; o >>= 1) v += __shfl_down_sync(0xFFFFFFFFu, v, o);
        if (threadIdx.x == 0) g_bsum[blockIdx.x] = v;
    }
}

// Kernel 3b: sum 40 block partials -> out
__global__ void finalize2_kernel(float* __restrict__ out) {
    const int t = threadIdx.x;
    float v = g_bsum[t] + ((t + 32 < 40) ? g_bsum[t + 32] : 0.f);
    #pragma unroll
    for (int o = 16; o > 0; o >>= 1) v += __shfl_down_sync(0xFFFFFFFFu, v, o);
    if (t == 0) out[0] = v;
}

// ============================================================================
extern "C" void kernel_launch(void* const* d_in, const int* in_sizes, int n_in,
                              void* d_out, int out_size) {
    const float* emb = (const float*)d_in[0];
    const float* w   = (const float*)d_in[1];
    const float* b   = (const float*)d_in[2];
    float* out = (float*)d_out;

    cudaFuncSetAttribute(gemm_kernel,
                         cudaFuncAttributeMaxDynamicSharedMemorySize, SMEM_DYN);

    prep_kernel<<<N_SPK, 256>>>(emb);
    gemm_kernel<<<dim3(MTILES, NTILES), 256, SMEM_DYN>>>(w, b);
    finalize1_kernel<<<40, 512>>>(w, b);
    finalize2_kernel<<<1, 32>>>(out);
}

// round 7
// speedup vs baseline: 1.4949x; 1.0120x over previous
#include <cuda_runtime.h>
#include <cuda_bf16.h>
#include <cstdint>

// ---------------- problem constants ----------------
static constexpr int N_SPK = 1024;
static constexpr int N_UTT = 20;
static constexpr int D_EMB = 512;
static constexpr int R_TOT = N_SPK * N_UTT;   // 20480 rows

static constexpr float COS_EPS = 1e-8f;
static constexpr float SIM_EPS = 1e-6f;

// ---------------- GEMM tiling ----------------
static constexpr int BM  = 128;               // rows per CTA
static constexpr int BN  = 128;               // centroid cols per CTA
static constexpr int KC  = 64;                // K chunk (bf16) -> 128B rows in smem
static constexpr int NCH = D_EMB / KC;        // 8 chunks
static constexpr int MTILES = R_TOT / BM;     // 160
static constexpr int NTILES = N_SPK / BN;     // 8
static constexpr int NPART  = NTILES;         // 8 row-sum partial arrays

// 3-stage ring: [A_s 16K | B_s 16K] x 3
static constexpr int STAGE_BYTES = 2 * BM * KC * 2;     // 32768
static constexpr int SMEM_DYN = 3 * STAGE_BYTES;        // 98304

// ---------------- scratch (device globals; no allocs allowed) ----------------
__device__ __nv_bfloat16 g_E[R_TOT * D_EMB];      // normalized embeddings (bf16)
__device__ __nv_bfloat16 g_C[N_SPK * D_EMB];      // normalized centroids (bf16)
__device__ float         g_diag[R_TOT];           // leave-one-out cosine (fp32)
__device__ float         g_rowsum[NPART][R_TOT];  // per n-tile exp sums
__device__ float         g_bsum[40];              // finalize partials

// ---------------- PTX helpers (plain-sm_103-safe) ----------------
__device__ __forceinline__ uint32_t smem_u32(const void* p) {
    uint32_t a;
    asm("{ .reg .u64 t; cvta.to.shared.u64 t, %1; cvt.u32.u64 %0, t; }"
        : "=r"(a) : "l"(p));
    return a;
}
__device__ __forceinline__ void cp16(uint32_t dst, const void* src) {
    asm volatile("cp.async.cg.shared.global [%0], [%1], 16;"
                 :: "r"(dst), "l"(src));
}
#define CP_COMMIT() asm volatile("cp.async.commit_group;" ::: "memory")
#define CP_WAIT(n)  asm volatile("cp.async.wait_group %0;" :: "n"(n) : "memory")

#define LDSM_X4(r0, r1, r2, r3, addr)                                          \
    asm volatile("ldmatrix.sync.aligned.m8n8.x4.shared.b16 {%0,%1,%2,%3}, [%4];" \
                 : "=r"(r0), "=r"(r1), "=r"(r2), "=r"(r3) : "r"(addr))

__device__ __forceinline__ void mma16816(float* c, const uint32_t* a,
                                         uint32_t b0, uint32_t b1) {
    asm volatile(
        "mma.sync.aligned.m16n8k16.row.col.f32.bf16.bf16.f32 "
        "{%0,%1,%2,%3}, {%4,%5,%6,%7}, {%8,%9}, {%0,%1,%2,%3};"
        : "+f"(c[0]), "+f"(c[1]), "+f"(c[2]), "+f"(c[3])
        : "r"(a[0]), "r"(a[1]), "r"(a[2]), "r"(a[3]), "r"(b0), "r"(b1));
}

// ============================================================================
// Kernel 1: per-speaker prep. One block per speaker, 8 warps.
// Work items 0..19 = utterances (warp-local reduce), item 20 = centroid.
// No block barriers inside the item loop.
// ============================================================================
__global__ void __launch_bounds__(256) prep_kernel(const float* __restrict__ emb) {
    __shared__ float sE[N_UTT * D_EMB];     // 40 KB
    __shared__ float sSum[D_EMB];           // 2 KB

    const int n    = blockIdx.x;
    const int tid  = threadIdx.x;
    const int wid  = tid >> 5;
    const int lane = tid & 31;

    // stage speaker block (2560 float4)
    const float4* src = reinterpret_cast<const float4*>(emb + (size_t)n * N_UTT * D_EMB);
    float4* dst = reinterpret_cast<float4*>(sE);
    #pragma unroll
    for (int i = tid; i < N_UTT * D_EMB / 4; i += 256) dst[i] = src[i];
    __syncthreads();

    // per-dim sums (each thread: d = tid, tid+256)
    #pragma unroll
    for (int dd = 0; dd < 2; dd++) {
        int d = tid + dd * 256;
        float s = 0.f;
        #pragma unroll
        for (int m = 0; m < N_UTT; m++) s += sE[m * D_EMB + d];
        sSum[d] = s;
    }
    __syncthreads();

    const float invM1 = 1.0f / (N_UTT - 1);

    for (int item = wid; item <= N_UTT; item += 8) {
        if (item == N_UTT) {
            // centroid: norm of sum, write normalized centroid
            float ss = 0.f;
            #pragma unroll
            for (int i = 0; i < 8; i++) {
                int d = i * 64 + lane * 2;
                float2 v = *reinterpret_cast<const float2*>(&sSum[d]);
                ss += v.x * v.x + v.y * v.y;
            }
            #pragma unroll
            for (int o = 16; o > 0; o >>= 1)
                ss += __shfl_xor_sync(0xFFFFFFFFu, ss, o);
            float cnorm  = sqrtf(ss) * (1.0f / N_UTT);
            float cscale = 1.0f / (N_UTT * fmaxf(cnorm, COS_EPS));
            #pragma unroll
            for (int i = 0; i < 8; i++) {
                int d = i * 64 + lane * 2;
                float2 v = *reinterpret_cast<const float2*>(&sSum[d]);
                __nv_bfloat162 o2;
                o2.x = __float2bfloat16(v.x * cscale);
                o2.y = __float2bfloat16(v.y * cscale);
                *reinterpret_cast<__nv_bfloat162*>(&g_C[(size_t)n * D_EMB + d]) = o2;
            }
        } else {
            const int m = item;
            float ee = 0.f, cc = 0.f, ec = 0.f;
            #pragma unroll
            for (int i = 0; i < 8; i++) {
                int d = i * 64 + lane * 2;
                float2 e  = *reinterpret_cast<const float2*>(&sE[m * D_EMB + d]);
                float2 s2 = *reinterpret_cast<const float2*>(&sSum[d]);
                float cx = (s2.x - e.x) * invM1;
                float cy = (s2.y - e.y) * invM1;
                ee += e.x * e.x + e.y * e.y;
                cc += cx * cx + cy * cy;
                ec += e.x * cx + e.y * cy;
            }
            #pragma unroll
            for (int o = 16; o > 0; o >>= 1) {
                ee += __shfl_xor_sync(0xFFFFFFFFu, ee, o);
                cc += __shfl_xor_sync(0xFFFFFFFFu, cc, o);
                ec += __shfl_xor_sync(0xFFFFFFFFu, ec, o);
            }
            float inv_e = 1.0f / fmaxf(sqrtf(ee), COS_EPS);
            float inv_c = 1.0f / fmaxf(sqrtf(cc), COS_EPS);
            if (lane == 0) g_diag[n * N_UTT + m] = ec * inv_e * inv_c;
            const size_t rowoff = (size_t)(n * N_UTT + m) * D_EMB;
            #pragma unroll
            for (int i = 0; i < 8; i++) {
                int d = i * 64 + lane * 2;
                float2 e = *reinterpret_cast<const float2*>(&sE[m * D_EMB + d]);
                __nv_bfloat162 o2;
                o2.x = __float2bfloat16(e.x * inv_e);
                o2.y = __float2bfloat16(e.y * inv_e);
                *reinterpret_cast<__nv_bfloat162*>(&g_E[rowoff + d]) = o2;
            }
        }
    }
}

// ---------------- async chunk load into 128B-row XOR-swizzled smem ----------
__device__ __forceinline__ void load_chunk_async(uint32_t As, uint32_t Bs,
                                                 int m_base, int n_base,
                                                 int c, int tid) {
    const int kof = c * KC;
    #pragma unroll
    for (int i = 0; i < 4; i++) {
        int g = tid + i * 256;
        int row = g >> 3, j = g & 7;
        const char* src = reinterpret_cast<const char*>(
            g_E + (size_t)(m_base + row) * D_EMB + kof) + j * 16;
        uint32_t dst = As + row * 128 + ((j * 16) ^ ((row & 7) * 16));
        cp16(dst, src);
    }
    #pragma unroll
    for (int i = 0; i < 4; i++) {
        int g = tid + i * 256;
        int row = g >> 3, j = g & 7;
        const char* src = reinterpret_cast<const char*>(
            g_C + (size_t)(n_base + row) * D_EMB + kof) + j * 16;
        uint32_t dst = Bs + row * 128 + ((j * 16) ^ ((row & 7) * 16));
        cp16(dst, src);
    }
}

// ============================================================================
// Kernel 2: mma.sync bf16 GEMM (128x128, K=512), 3-stage cp.async ring,
// one __syncthreads per chunk, fused exp-sum epilogue.
// grid = (MTILES, NTILES), block = 256 (8 warps: warp_m = wid&3, warp_n = wid>>2)
// ============================================================================
__global__ void __launch_bounds__(256, 2) gemm_kernel(const float* __restrict__ wp,
                                                      const float* __restrict__ bp) {
    extern __shared__ char dsm[];
    const uint32_t sb = smem_u32(dsm);
    const uint32_t aAddr[3] = { sb,               sb + STAGE_BYTES,
                                sb + 2 * STAGE_BYTES };
    const uint32_t bAddr[3] = { sb + 16384,       sb + STAGE_BYTES + 16384,
                                sb + 2 * STAGE_BYTES + 16384 };

    const int tid  = threadIdx.x;
    const int wid  = tid >> 5;
    const int lane = tid & 31;
    const int warp_m = wid & 3;
    const int warp_n = wid >> 2;
    const int m_base = blockIdx.x * BM;
    const int n_base = blockIdx.y * BN;

    float acc[2][8][4];
    #pragma unroll
    for (int mi = 0; mi < 2; mi++)
        #pragma unroll
        for (int ni = 0; ni < 8; ni++)
            #pragma unroll
            for (int k = 0; k < 4; k++) acc[mi][ni][k] = 0.f;

    const int rowA0 = warp_m * 32 + (lane & 15);
    const int gA    = lane >> 4;
    const int rowB0 = warp_n * 64 + (lane & 7) + (((lane >> 4) & 1) << 3);
    const int gBsel = (lane >> 3) & 1;

    load_chunk_async(aAddr[0], bAddr[0], m_base, n_base, 0, tid);
    CP_COMMIT();
    load_chunk_async(aAddr[1], bAddr[1], m_base, n_base, 1, tid);
    CP_COMMIT();

    #pragma unroll
    for (int c = 0; c < NCH; c++) {
        if (c + 1 < NCH) { CP_WAIT(1); } else { CP_WAIT(0); }
        __syncthreads();
        if (c + 2 < NCH) {
            const int s = (c + 2) % 3;
            load_chunk_async(aAddr[s], bAddr[s], m_base, n_base, c + 2, tid);
            CP_COMMIT();
        }
        const uint32_t As = aAddr[c % 3], Bs = bAddr[c % 3];
        #pragma unroll
        for (int ks = 0; ks < 4; ks++) {
            uint32_t a[2][4];
            #pragma unroll
            for (int mi = 0; mi < 2; mi++) {
                int rowA = rowA0 + mi * 16;
                uint32_t addr = As + rowA * 128 +
                                (((ks * 2 + gA) * 16) ^ ((rowA & 7) * 16));
                LDSM_X4(a[mi][0], a[mi][1], a[mi][2], a[mi][3], addr);
            }
            #pragma unroll
            for (int p = 0; p < 4; p++) {
                int rowB = rowB0 + p * 16;
                int gB = ks * 2 + gBsel;
                uint32_t addr = Bs + rowB * 128 + ((gB * 16) ^ ((rowB & 7) * 16));
                uint32_t b0, b1, b2, b3;
                LDSM_X4(b0, b1, b2, b3, addr);
                mma16816(acc[0][2 * p],     a[0], b0, b1);
                mma16816(acc[0][2 * p + 1], a[0], b2, b3);
                mma16816(acc[1][2 * p],     a[1], b0, b1);
                mma16816(acc[1][2 * p + 1], a[1], b2, b3);
            }
        }
    }

    // ---- fused epilogue: exp-sum per row, leave-one-out replacement,
    //      combine the two warp_n halves through smem -> one partial per CTA ----
    const float wv  = *wp;
    const float bpr = fmaf(wv, SIM_EPS, *bp);
    const int l4 = lane >> 2, lm = lane & 3;
    const int colbase = n_base + warp_n * 64 + 2 * lm;
    float* sPart = reinterpret_cast<float*>(dsm);   // stage-0 region, safe now

    float rowS[2][2];
    #pragma unroll
    for (int mi = 0; mi < 2; mi++) {
        #pragma unroll
        for (int h = 0; h < 2; h++) {
            const int rg = m_base + warp_m * 32 + mi * 16 + h * 8 + l4;
            const int spk = rg / N_UTT;
            const float dval = g_diag[rg];
            float s = 0.f;
            #pragma unroll
            for (int ni = 0; ni < 8; ni++) {
                #pragma unroll
                for (int cc = 0; cc < 2; cc++) {
                    float cv = acc[mi][ni][2 * h + cc];
                    int col = colbase + ni * 8 + cc;
                    if (col == spk) cv = dval;
                    s += __expf(fmaf(wv, cv, bpr));
                }
            }
            s += __shfl_xor_sync(0xFFFFFFFFu, s, 1);
            s += __shfl_xor_sync(0xFFFFFFFFu, s, 2);
            rowS[mi][h] = s;
        }
    }
    __syncthreads();   // all warps done with smem tiles + ready for sPart
    if (warp_n == 0 && lm == 0) {
        #pragma unroll
        for (int mi = 0; mi < 2; mi++)
            #pragma unroll
            for (int h = 0; h < 2; h++)
                sPart[warp_m * 32 + mi * 16 + h * 8 + l4] = rowS[mi][h];
    }
    __syncthreads();
    if (warp_n == 1 && lm == 0) {
        #pragma unroll
        for (int mi = 0; mi < 2; mi++)
            #pragma unroll
            for (int h = 0; h < 2; h++) {
                const int idx = warp_m * 32 + mi * 16 + h * 8 + l4;
                g_rowsum[blockIdx.y][m_base + idx] = rowS[mi][h] + sPart[idx];
            }
    }
}

// ============================================================================
// Kernel 3a: per-row log-sum-exp minus pos, block-reduced. grid=40 x 512 thr
// ============================================================================
__global__ void __launch_bounds__(512) finalize1_kernel(const float* __restrict__ wp,
                                                        const float* __restrict__ bp) {
    __shared__ float sRed[16];
    const int r = blockIdx.x * 512 + threadIdx.x;
    const float wv = *wp, bv = *bp;
    float s = 0.f;
    #pragma unroll
    for (int p = 0; p < NPART; p++) s += g_rowsum[p][r];
    float acc = logf(s + SIM_EPS) - fmaf(wv, g_diag[r] + SIM_EPS, bv);
    #pragma unroll
    for (int o = 16; o > 0; o >>= 1) acc += __shfl_down_sync(0xFFFFFFFFu, acc, o);
    if ((threadIdx.x & 31) == 0) sRed[threadIdx.x >> 5] = acc;
    __syncthreads();
    if (threadIdx.x < 32) {
        float v = (threadIdx.x < 16) ? sRed[threadIdx.x] : 0.f;
        #pragma unroll
        for (int o = 8; o > 0; o >>= 1) v += __shfl_down_sync(0xFFFFFFFFu, v, o);
        if (threadIdx.x == 0) g_bsum[blockIdx.x] = v;
    }
}

// Kernel 3b: sum 40 block partials -> out
__global__ void finalize2_kernel(float* __restrict__ out) {
    const int t = threadIdx.x;
    float v = g_bsum[t] + ((t + 32 < 40) ? g_bsum[t + 32] : 0.f);
    #pragma unroll
    for (int o = 16; o > 0; o >>= 1) v += __shfl_down_sync(0xFFFFFFFFu, v, o);
    if (t == 0) out[0] = v;
}

// ============================================================================
extern "C" void kernel_launch(void* const* d_in, const int* in_sizes, int n_in,
                              void* d_out, int out_size) {
    const float* emb = (const float*)d_in[0];
    const float* w   = (const float*)d_in[1];
    const float* b   = (const float*)d_in[2];
    float* out = (float*)d_out;

    cudaFuncSetAttribute(gemm_kernel,
                         cudaFuncAttributeMaxDynamicSharedMemorySize, SMEM_DYN);

    prep_kernel<<<N_SPK, 256>>>(emb);
    gemm_kernel<<<dim3(MTILES, NTILES), 256, SMEM_DYN>>>(w, b);
    finalize1_kernel<<<40, 512>>>(w, b);
    finalize2_kernel<<<1, 32>>>(out);
}